// round 1
// baseline (speedup 1.0000x reference)
#include <cuda_runtime.h>
#include <math.h>

#define FULLMASK 0xffffffffu

// ---------------- scratch (device globals; no allocations allowed) ----------
__device__ int      g_idx[4 * 4096 * 32];     // ball-query indices   (2 MB)
__device__ float    g_abs[4 * 4096 * 96];     // absolute sin-emb     (6 MB)
__device__ unsigned g_pooled[4 * 256];        // order-keyed max pool

// ---------------- small helpers --------------------------------------------
__device__ __forceinline__ unsigned long long pk2(float a, float b) {
    unsigned long long r;
    asm("mov.b64 %0, {%1, %2};" : "=l"(r) : "f"(a), "f"(b));
    return r;
}
__device__ __forceinline__ void upk2(unsigned long long v, float& a, float& b) {
    asm("mov.b64 {%0, %1}, %2;" : "=f"(a), "=f"(b) : "l"(v));
}
// packed fp32x2 FMA: d = a*b + d   (2 FMAs / instruction on sm_103a)
__device__ __forceinline__ void ffma2(unsigned long long& d, unsigned long long a,
                                      unsigned long long b) {
    asm("fma.rn.f32x2 %0, %1, %2, %0;" : "+l"(d) : "l"(a), "l"(b));
}
// order-preserving float<->uint map for atomicMax
__device__ __forceinline__ unsigned fkey(float f) {
    int i = __float_as_int(f);
    return (i >= 0) ? ((unsigned)i | 0x80000000u) : ~(unsigned)i;
}
__device__ __forceinline__ float funkey(unsigned u) {
    int i = (u & 0x80000000u) ? (int)(u & 0x7fffffffu) : (int)(~u);
    return __int_as_float(i);
}
__device__ __forceinline__ float gelu_exact(float x) {
    return 0.5f * x * (1.0f + erff(x * 0.70710678118654752f));
}

// ---------------- kernel 0: init pooled max to -inf key ---------------------
__global__ void k_init() {
    int t = blockIdx.x * blockDim.x + threadIdx.x;
    if (t < 1024) g_pooled[t] = 0x007FFFFFu;   // fkey(-inf)
}

// ---------------- kernel 1: ball query + absolute position embedding --------
// grid (N/8, B), 256 threads. One warp per query point, xyz staged in SMEM.
__global__ __launch_bounds__(256) void k_ball(const float* __restrict__ xyz) {
    __shared__ float sx[4096], sy[4096], sz[4096];
    const int b = blockIdx.y;
    const float* base = xyz + (size_t)b * 4096 * 3;
    for (int i = threadIdx.x; i < 4096; i += 256) {
        float3 v = *(const float3*)(base + 3 * i);
        sx[i] = v.x; sy[i] = v.y; sz[i] = v.z;
    }
    __syncthreads();

    const int lane = threadIdx.x & 31, warp = threadIdx.x >> 5;
    const int n = blockIdx.x * 8 + warp;
    const float qx = sx[n], qy = sy[n], qz = sz[n];
    const int p = (b << 12) + n;

    int cnt = 0, fm = n;
    for (int c = 0; c < 128; c++) {
        int m = c * 32 + lane;
        float dx = sx[m] - qx, dy = sy[m] - qy, dz = sz[m] - qz;
        // match JAX rounding: mul/add, NO fma contraction
        float sq = __fadd_rn(__fadd_rn(__fmul_rn(dx, dx), __fmul_rn(dy, dy)),
                             __fmul_rn(dz, dz));
        bool in = (sq <= 0.0256f);                 // exclude only sq > r^2
        unsigned mask = __ballot_sync(FULLMASK, in);
        if (mask) {
            if (cnt == 0) fm = c * 32 + (__ffs(mask) - 1);  // first in-ball index
            if (in) {
                int pos = cnt + __popc(mask & ((1u << lane) - 1u));
                if (pos < 32) g_idx[p * 32 + pos] = m;
            }
            cnt += __popc(mask);
            if (cnt >= 32) break;
        }
    }
    for (int k = cnt + lane; k < 32; k += 32) g_idx[p * 32 + k] = fm;  // pad

    // absolute sin-emb: dim 96 = 3 axes * (16 sin + 16 cos)
    int jj = lane & 15;
    float fr = expf((-logf(10000.0f) * (float)jj) / 15.0f);
    float co[3] = {qx, qy, qz};
#pragma unroll
    for (int a = 0; a < 3; a++) {
        float ang = co[a] * fr;
        g_abs[(size_t)p * 96 + a * 32 + lane] = (lane >= 16) ? cosf(ang) : sinf(ang);
    }
}

// ---------------- kernel 2: fused MLP(187->256->256) + joint max pool -------
// 64 rows (= 2 query points x K=32) per block, 256 threads.
// thread microtile: 8 rows x 8 cols; each warp owns 8 whole rows -> LN via shfl.
#define LDX 192
#define SMEM_MLP ((64 * LDX + 64 * 256 + 32 * 256) * 4 + 64 * 4)

__global__ __launch_bounds__(256) void k_mlp(
    const float* __restrict__ xyz, const float* __restrict__ pf,
    const float* __restrict__ w1, const float* __restrict__ b1,
    const float* __restrict__ g1, const float* __restrict__ be1,
    const float* __restrict__ w2, const float* __restrict__ b2,
    const float* __restrict__ g2, const float* __restrict__ be2) {
    extern __shared__ float sm[];
    float* Xs = sm;                      // 64 x 192  (187 + zero pad)
    float* Hs = Xs + 64 * LDX;           // 64 x 256
    float* Wb = Hs + 64 * 256;           // 32 x 256 weight chunk (reused as red)
    int* sm_m = (int*)(Wb + 32 * 256);   // 64 neighbor ids

    const int t = threadIdx.x, lane = t & 31, warp = t >> 5;
    const int p0 = blockIdx.x * 2;
    const int b = p0 >> 12;

    // ---- build input rows X[i][0..186] -------------------------------------
    if (t < 64) {
        int p = p0 + (t >> 5);
        int n = p & 4095;
        int m = g_idx[p * 32 + (t & 31)];
        sm_m[t] = m;
        const float* xm = xyz + ((size_t)(b << 12) + m) * 3;
        const float* xn = xyz + ((size_t)(b << 12) + n) * 3;
        float* Xr = Xs + t * LDX;
        Xr[64] = xm[0] - xn[0];
        Xr[65] = xm[1] - xn[1];
        Xr[66] = xm[2] - xn[2];
        Xr[187] = 0.f; Xr[188] = 0.f; Xr[189] = 0.f; Xr[190] = 0.f; Xr[191] = 0.f;
    }
    for (int e = t; e < 64 * 96; e += 256) {           // absolute emb (shared per point)
        int i = e / 96, j = e - 96 * i;
        int p = p0 + (i >> 5);
        Xs[i * LDX + 91 + j] = g_abs[(size_t)p * 96 + j];
    }
    __syncthreads();
    for (int e = t; e < 64 * 64; e += 256) {           // grouped features
        int i = e >> 6, j = e & 63;
        Xs[i * LDX + j] = pf[(((size_t)(b << 12)) + sm_m[i]) * 64 + j];
    }
    for (int e = t; e < 64 * 24; e += 256) {           // relative sin-emb (24)
        int i = e / 24, j = e - 24 * i;
        int a = j >> 3, jj = j & 7;
        float rel = Xs[i * LDX + 64 + a];
        float fr = expf((-logf(10000.0f) * (float)(jj & 3)) / 3.0f);
        float ang = rel * fr;
        Xs[i * LDX + 67 + j] = (jj < 4) ? sinf(ang) : cosf(ang);
    }

    const int c0 = lane * 8;
    unsigned long long acc[8][4];

    // =================== layer 1: X[64x187(192)] @ W1 -> acc =================
    {
        unsigned long long bias[4];
#pragma unroll
        for (int q = 0; q < 4; q++)
            bias[q] = pk2(__ldg(&b1[c0 + 2 * q]), __ldg(&b1[c0 + 2 * q + 1]));
#pragma unroll
        for (int r = 0; r < 8; r++)
#pragma unroll
            for (int q = 0; q < 4; q++) acc[r][q] = bias[q];

        for (int kb = 0; kb < 192; kb += 32) {
            __syncthreads();
            for (int v = t; v < 2048; v += 256) {
                int kk = kb + (v >> 6);
                float4 val = (kk < 187) ? __ldg(&((const float4*)w1)[kk * 64 + (v & 63)])
                                        : make_float4(0.f, 0.f, 0.f, 0.f);
                ((float4*)Wb)[v] = val;
            }
            __syncthreads();
            const float* Sc = Xs + warp * 8 * LDX + kb;
#pragma unroll 2
            for (int kl = 0; kl < 32; kl += 4) {
                float4 xq[8];
#pragma unroll
                for (int r = 0; r < 8; r++)
                    xq[r] = *(const float4*)(Sc + r * LDX + kl);
#pragma unroll
                for (int s = 0; s < 4; s++) {
                    ulonglong2 wa = *(const ulonglong2*)(Wb + (kl + s) * 256 + c0);
                    ulonglong2 wc = *(const ulonglong2*)(Wb + (kl + s) * 256 + c0 + 4);
#pragma unroll
                    for (int r = 0; r < 8; r++) {
                        float xv = (s == 0) ? xq[r].x : (s == 1) ? xq[r].y
                                  : (s == 2) ? xq[r].z : xq[r].w;
                        unsigned long long x2 = pk2(xv, xv);
                        ffma2(acc[r][0], x2, wa.x);
                        ffma2(acc[r][1], x2, wa.y);
                        ffma2(acc[r][2], x2, wc.x);
                        ffma2(acc[r][3], x2, wc.y);
                    }
                }
            }
        }
    }

    // ---- LN1 + exact GELU -> Hs --------------------------------------------
    {
        float gg[8], bb[8];
#pragma unroll
        for (int j = 0; j < 8; j++) { gg[j] = __ldg(&g1[c0 + j]); bb[j] = __ldg(&be1[c0 + j]); }
#pragma unroll
        for (int r = 0; r < 8; r++) {
            float v[8];
            upk2(acc[r][0], v[0], v[1]); upk2(acc[r][1], v[2], v[3]);
            upk2(acc[r][2], v[4], v[5]); upk2(acc[r][3], v[6], v[7]);
            float s = 0.f;
#pragma unroll
            for (int j = 0; j < 8; j++) s += v[j];
#pragma unroll
            for (int o = 16; o; o >>= 1) s += __shfl_xor_sync(FULLMASK, s, o);
            float mu = s * (1.0f / 256.0f);
            float d[8]; float ss = 0.f;
#pragma unroll
            for (int j = 0; j < 8; j++) { d[j] = v[j] - mu; ss += d[j] * d[j]; }
#pragma unroll
            for (int o = 16; o; o >>= 1) ss += __shfl_xor_sync(FULLMASK, ss, o);
            float inv = rsqrtf(ss * (1.0f / 256.0f) + 1e-5f);
            float* Hr = Hs + (warp * 8 + r) * 256 + c0;
#pragma unroll
            for (int j = 0; j < 8; j++) {
                float h = d[j] * inv * gg[j] + bb[j];
                Hr[j] = gelu_exact(h);
            }
        }
    }

    // =================== layer 2: H[64x256] @ W2 -> acc ======================
    {
        unsigned long long bias[4];
#pragma unroll
        for (int q = 0; q < 4; q++)
            bias[q] = pk2(__ldg(&b2[c0 + 2 * q]), __ldg(&b2[c0 + 2 * q + 1]));
#pragma unroll
        for (int r = 0; r < 8; r++)
#pragma unroll
            for (int q = 0; q < 4; q++) acc[r][q] = bias[q];

        for (int kb = 0; kb < 256; kb += 32) {
            __syncthreads();
            for (int v = t; v < 2048; v += 256) {
                int kk = kb + (v >> 6);
                ((float4*)Wb)[v] = __ldg(&((const float4*)w2)[kk * 64 + (v & 63)]);
            }
            __syncthreads();
            const float* Sc = Hs + warp * 8 * 256 + kb;
#pragma unroll 2
            for (int kl = 0; kl < 32; kl += 4) {
                float4 xq[8];
#pragma unroll
                for (int r = 0; r < 8; r++)
                    xq[r] = *(const float4*)(Sc + r * 256 + kl);
#pragma unroll
                for (int s = 0; s < 4; s++) {
                    ulonglong2 wa = *(const ulonglong2*)(Wb + (kl + s) * 256 + c0);
                    ulonglong2 wc = *(const ulonglong2*)(Wb + (kl + s) * 256 + c0 + 4);
#pragma unroll
                    for (int r = 0; r < 8; r++) {
                        float xv = (s == 0) ? xq[r].x : (s == 1) ? xq[r].y
                                  : (s == 2) ? xq[r].z : xq[r].w;
                        unsigned long long x2 = pk2(xv, xv);
                        ffma2(acc[r][0], x2, wa.x);
                        ffma2(acc[r][1], x2, wa.y);
                        ffma2(acc[r][2], x2, wc.x);
                        ffma2(acc[r][3], x2, wc.y);
                    }
                }
            }
        }
    }

    // ---- LN2 + per-thread max over its 8 rows -------------------------------
    float mcol[8];
#pragma unroll
    for (int j = 0; j < 8; j++) mcol[j] = -INFINITY;
    {
        float gg[8], bb[8];
#pragma unroll
        for (int j = 0; j < 8; j++) { gg[j] = __ldg(&g2[c0 + j]); bb[j] = __ldg(&be2[c0 + j]); }
#pragma unroll
        for (int r = 0; r < 8; r++) {
            float v[8];
            upk2(acc[r][0], v[0], v[1]); upk2(acc[r][1], v[2], v[3]);
            upk2(acc[r][2], v[4], v[5]); upk2(acc[r][3], v[6], v[7]);
            float s = 0.f;
#pragma unroll
            for (int j = 0; j < 8; j++) s += v[j];
#pragma unroll
            for (int o = 16; o; o >>= 1) s += __shfl_xor_sync(FULLMASK, s, o);
            float mu = s * (1.0f / 256.0f);
            float d[8]; float ss = 0.f;
#pragma unroll
            for (int j = 0; j < 8; j++) { d[j] = v[j] - mu; ss += d[j] * d[j]; }
#pragma unroll
            for (int o = 16; o; o >>= 1) ss += __shfl_xor_sync(FULLMASK, ss, o);
            float inv = rsqrtf(ss * (1.0f / 256.0f) + 1e-5f);
#pragma unroll
            for (int j = 0; j < 8; j++) {
                float y = d[j] * inv * gg[j] + bb[j];
                mcol[j] = fmaxf(mcol[j], y);
            }
        }
    }

    // ---- block max (reuse Wb) then global atomic max ------------------------
    __syncthreads();
    float* red = Wb;   // 8 x 256
#pragma unroll
    for (int j = 0; j < 8; j++) red[warp * 256 + c0 + j] = mcol[j];
    __syncthreads();
    {
        int c = t;
        float mm = red[c];
#pragma unroll
        for (int w = 1; w < 8; w++) mm = fmaxf(mm, red[w * 256 + c]);
        atomicMax(&g_pooled[(b << 8) + c], fkey(mm));
    }
}

// ---------------- kernel 3: final 4-row MLP ---------------------------------
__device__ __forceinline__ float bsum256(float v, float* sred) {
#pragma unroll
    for (int o = 16; o; o >>= 1) v += __shfl_xor_sync(FULLMASK, v, o);
    if ((threadIdx.x & 31) == 0) sred[threadIdx.x >> 5] = v;
    __syncthreads();
    float s = 0.f;
#pragma unroll
    for (int w = 0; w < 8; w++) s += sred[w];
    __syncthreads();
    return s;
}

__global__ __launch_bounds__(256) void k_final(
    const float* __restrict__ pw1, const float* __restrict__ pb1,
    const float* __restrict__ pg1, const float* __restrict__ pbe1,
    const float* __restrict__ pw2, const float* __restrict__ pb2,
    const float* __restrict__ pg2, const float* __restrict__ pbe2,
    float* __restrict__ out) {
    __shared__ float xin[4][256];
    __shared__ float hh[4][256];
    __shared__ float sred[8];
    const int t = threadIdx.x;
    for (int i = t; i < 1024; i += 256) ((float*)xin)[i] = funkey(g_pooled[i]);
    __syncthreads();

    float acc[4];
#pragma unroll
    for (int b = 0; b < 4; b++) acc[b] = pb1[t];
    for (int k = 0; k < 256; k++) {
        float w = pw1[k * 256 + t];
#pragma unroll
        for (int b = 0; b < 4; b++) acc[b] = fmaf(xin[b][k], w, acc[b]);
    }
#pragma unroll
    for (int b = 0; b < 4; b++) hh[b][t] = acc[b];
    __syncthreads();
    for (int b = 0; b < 4; b++) {
        float val = hh[b][t];
        float mu = bsum256(val, sred) * (1.0f / 256.0f);
        float d = val - mu;
        float var = bsum256(d * d, sred) * (1.0f / 256.0f);
        float y = d * rsqrtf(var + 1e-5f) * pg1[t] + pbe1[t];
        xin[b][t] = gelu_exact(y);
    }
    __syncthreads();
#pragma unroll
    for (int b = 0; b < 4; b++) acc[b] = pb2[t];
    for (int k = 0; k < 256; k++) {
        float w = pw2[k * 256 + t];
#pragma unroll
        for (int b = 0; b < 4; b++) acc[b] = fmaf(xin[b][k], w, acc[b]);
    }
#pragma unroll
    for (int b = 0; b < 4; b++) hh[b][t] = acc[b];
    __syncthreads();
    for (int b = 0; b < 4; b++) {
        float val = hh[b][t];
        float mu = bsum256(val, sred) * (1.0f / 256.0f);
        float d = val - mu;
        float var = bsum256(d * d, sred) * (1.0f / 256.0f);
        out[b * 256 + t] = d * rsqrtf(var + 1e-5f) * pg2[t] + pbe2[t];
    }
}

// ---------------- launcher ---------------------------------------------------
extern "C" void kernel_launch(void* const* d_in, const int* in_sizes, int n_in,
                              void* d_out, int out_size) {
    const float* xyz  = (const float*)d_in[0];
    const float* pf   = (const float*)d_in[1];
    const float* w1   = (const float*)d_in[2];
    const float* b1   = (const float*)d_in[3];
    const float* g1   = (const float*)d_in[4];
    const float* be1  = (const float*)d_in[5];
    const float* w2   = (const float*)d_in[6];
    const float* b2   = (const float*)d_in[7];
    const float* g2   = (const float*)d_in[8];
    const float* be2  = (const float*)d_in[9];
    const float* pw1  = (const float*)d_in[10];
    const float* pb1  = (const float*)d_in[11];
    const float* pg1  = (const float*)d_in[12];
    const float* pbe1 = (const float*)d_in[13];
    const float* pw2  = (const float*)d_in[14];
    const float* pb2  = (const float*)d_in[15];
    const float* pg2  = (const float*)d_in[16];
    const float* pbe2 = (const float*)d_in[17];
    float* out = (float*)d_out;

    cudaFuncSetAttribute(k_mlp, cudaFuncAttributeMaxDynamicSharedMemorySize, SMEM_MLP);

    k_init<<<4, 256>>>();
    k_ball<<<dim3(512, 4), 256>>>(xyz);
    k_mlp<<<8192, 256, SMEM_MLP>>>(xyz, pf, w1, b1, g1, be1, w2, b2, g2, be2);
    k_final<<<1, 256>>>(pw1, pb1, pg1, pbe1, pw2, pb2, pg2, pbe2, out);
}